// round 5
// baseline (speedup 1.0000x reference)
#include <cuda_runtime.h>
#include <cuda_fp16.h>

#define H 1024
#define W 1024
#define PLANES 24              // 8 * 3
#define THRAW 32               // raw output rows per tile
#define PACK 16                // row-pack stride (.x = r, .y = r+16)
#define TW 128                 // tile cols
#define RE 8                   // cols per thread
#define BX 16
#define BY 16                  // packed rows per tile
#define PROWS (BY + 3)         // 19 packed rows (k halo)
#define SCOLS (TW + 8)         // 136 (col halo: -4..+3 extra)
#define NBX (W / TW)           // 8
#define NBY (H / THRAW)        // 32
#define NBLOCKS (NBX * NBY * PLANES)  // 6144

__device__ float g_partials[NBLOCKS];
__device__ int g_ctr = 0;

// Load a 16-wide half2 window from shared row, rotated chunk order so the
// 2-way bank conflict between lanes (tx, tx+4) never materializes.
#define LOADROW(wdst, srow, txv)                                              \
    do {                                                                      \
        const float4* rowp = reinterpret_cast<const float4*>(&(srow)[(txv) * RE]); \
        _Pragma("unroll")                                                     \
        for (int j = 0; j < 4; ++j) {                                         \
            int q = (j + ((txv) >> 2)) & 3;                                   \
            float4 v = rowp[q];                                               \
            (wdst)[4 * q + 0] = *(__half2*)&v.x;                              \
            (wdst)[4 * q + 1] = *(__half2*)&v.y;                              \
            (wdst)[4 * q + 2] = *(__half2*)&v.z;                              \
            (wdst)[4 * q + 3] = *(__half2*)&v.w;                              \
        }                                                                     \
    } while (0)

__global__ __launch_bounds__(BX * BY) void btv_kernel(const float* __restrict__ x,
                                                      float* __restrict__ out) {
    __shared__ __align__(16) __half2 s[PROWS][SCOLS];
    __shared__ float warp_sums[(BX * BY) / 32];
    __shared__ int s_last;

    const int tx = threadIdx.x;
    const int ty = threadIdx.y;
    const int tid = ty * BX + tx;

    const int tile_x = blockIdx.x * TW;
    const int tile_y = blockIdx.y * THRAW;
    const float* plane = x + (size_t)blockIdx.z * (H * W);

    // Cooperative load: packed row pr holds raw rows (tile_y+pr, tile_y+pr+16).
    for (int idx = tid; idx < PROWS * SCOLS; idx += BX * BY) {
        int r = idx / SCOLS;
        int c = idx - r * SCOLS;
        int gr0 = (tile_y + r) & (H - 1);
        int gr1 = (tile_y + r + PACK) & (H - 1);
        int gc = (tile_x + c - 4) & (W - 1);
        float v0 = plane[gr0 * W + gc];
        float v1 = plane[gr1 * W + gc];
        s[r][c] = __floats2half2_rn(v0, v1);
    }
    __syncthreads();

    __half2 c2[RE];
    __half2 acc[RE];
#pragma unroll
    for (int e = 0; e < RE; e++) acc[e] = __floats2half2_rn(0.0f, 0.0f);

    __half2 win0[16], win1[16];

    // Pipeline: load k=0 and k=1 windows up front.
    LOADROW(win0, s[ty], tx);
    LOADROW(win1, s[ty + 1], tx);

#pragma unroll
    for (int e = 0; e < RE; e++) c2[e] = win0[4 + e];

    // k = 0: dl = 1..3 (symmetry covers negatives)
#pragma unroll
    for (int dl = 1; dl <= 3; dl++) {
#pragma unroll
        for (int e = 0; e < RE; e++) {
            __half2 d = __habs2(__hsub2(c2[e], win0[4 + e + dl]));
            acc[e] = __hadd2(acc[e], d);
        }
    }

    // Prefetch k=2 row into win0, then compute k=1 from win1.
    LOADROW(win0, s[ty + 2], tx);
#pragma unroll
    for (int dl = -3; dl <= 3; dl++) {
#pragma unroll
        for (int e = 0; e < RE; e++) {
            __half2 d = __habs2(__hsub2(c2[e], win1[4 + e + dl]));
            acc[e] = __hadd2(acc[e], d);
        }
    }

    // Prefetch k=3 row into win1, then compute k=2 from win0.
    LOADROW(win1, s[ty + 3], tx);
#pragma unroll
    for (int dl = -3; dl <= 3; dl++) {
#pragma unroll
        for (int e = 0; e < RE; e++) {
            __half2 d = __habs2(__hsub2(c2[e], win0[4 + e + dl]));
            acc[e] = __hadd2(acc[e], d);
        }
    }

    // k = 3 from win1.
#pragma unroll
    for (int dl = -3; dl <= 3; dl++) {
#pragma unroll
        for (int e = 0; e < RE; e++) {
            __half2 d = __habs2(__hsub2(c2[e], win1[4 + e + dl]));
            acc[e] = __hadd2(acc[e], d);
        }
    }

    // Widen to fp32 and reduce
    float accf = 0.0f;
#pragma unroll
    for (int e = 0; e < RE; e++) {
        float2 f = __half22float2(acc[e]);
        accf += f.x + f.y;
    }

#pragma unroll
    for (int o = 16; o > 0; o >>= 1) accf += __shfl_down_sync(0xFFFFFFFFu, accf, o);

    const int lane = tid & 31;
    const int wid = tid >> 5;
    if (lane == 0) warp_sums[wid] = accf;
    __syncthreads();

    if (tid == 0) {
        float bsum = 0.0f;
#pragma unroll
        for (int i = 0; i < (BX * BY) / 32; i++) bsum += warp_sums[i];
        int bidx = (blockIdx.z * gridDim.y + blockIdx.y) * gridDim.x + blockIdx.x;
        g_partials[bidx] = bsum;
        __threadfence();
        int done = atomicAdd(&g_ctr, 1);
        s_last = (done == NBLOCKS - 1) ? 1 : 0;
    }
    __syncthreads();

    // Last block reduces all partials (fixed order -> deterministic)
    if (s_last) {
        double t = 0.0;
        for (int i = tid; i < NBLOCKS; i += BX * BY) t += (double)g_partials[i];
#pragma unroll
        for (int o = 16; o > 0; o >>= 1) t += __shfl_down_sync(0xFFFFFFFFu, t, o);
        __shared__ double sm[(BX * BY) / 32];
        if (lane == 0) sm[wid] = t;
        __syncthreads();
        if (tid == 0) {
            double r = 0.0;
#pragma unroll
            for (int i = 0; i < (BX * BY) / 32; i++) r += sm[i];
            // symmetry factor 2; WEIGHT=0.1; N = 24*1024*1024
            out[0] = (float)(r * (0.2 / 25165824.0));
            atomicExch(&g_ctr, 0);  // reset for next graph replay
        }
    }
}

extern "C" void kernel_launch(void* const* d_in, const int* in_sizes, int n_in,
                              void* d_out, int out_size) {
    (void)in_sizes; (void)n_in; (void)out_size;
    const float* x = (const float*)d_in[0];
    float* out = (float*)d_out;

    dim3 grid(NBX, NBY, PLANES);
    dim3 block(BX, BY);
    btv_kernel<<<grid, block>>>(x, out);
}

// round 6
// speedup vs baseline: 2.2892x; 2.2892x over previous
#include <cuda_runtime.h>
#include <cuda_fp16.h>

#define H 1024
#define W 1024
#define PLANES 24              // 8 * 3
#define THRAW 32               // raw output rows per tile
#define PACK 16                // row-pack stride (.x = r, .y = r+16)
#define TW 128                 // tile cols
#define RE 8                   // cols per thread
#define BX 16
#define BY 16                  // packed rows per tile
#define PROWS (BY + 3)         // 19 packed rows (k halo)
#define SCOLS (TW + 8)         // 136 (col halo: -4..+3 extra)
#define NBX (W / TW)           // 8
#define NBY (H / THRAW)        // 32
#define NBLOCKS (NBX * NBY * PLANES)  // 6144

__device__ float g_partials[NBLOCKS];
__device__ int g_ctr = 0;

// Straight-order window load: all register indices compile-time constant.
#define LOADROW(wdst, srow, txv)                                                   \
    do {                                                                           \
        const float4* rowp = reinterpret_cast<const float4*>(&(srow)[(txv) * RE]); \
        float4 v0 = rowp[0], v1 = rowp[1], v2 = rowp[2], v3 = rowp[3];             \
        (wdst)[0] = *(__half2*)&v0.x;  (wdst)[1] = *(__half2*)&v0.y;               \
        (wdst)[2] = *(__half2*)&v0.z;  (wdst)[3] = *(__half2*)&v0.w;               \
        (wdst)[4] = *(__half2*)&v1.x;  (wdst)[5] = *(__half2*)&v1.y;               \
        (wdst)[6] = *(__half2*)&v1.z;  (wdst)[7] = *(__half2*)&v1.w;               \
        (wdst)[8] = *(__half2*)&v2.x;  (wdst)[9] = *(__half2*)&v2.y;               \
        (wdst)[10] = *(__half2*)&v2.z; (wdst)[11] = *(__half2*)&v2.w;              \
        (wdst)[12] = *(__half2*)&v3.x; (wdst)[13] = *(__half2*)&v3.y;              \
        (wdst)[14] = *(__half2*)&v3.z; (wdst)[15] = *(__half2*)&v3.w;              \
    } while (0)

__global__ __launch_bounds__(BX * BY, 3) void btv_kernel(const float* __restrict__ x,
                                                         float* __restrict__ out) {
    __shared__ __align__(16) __half2 s[PROWS][SCOLS];
    __shared__ float warp_sums[(BX * BY) / 32];
    __shared__ int s_last;

    const int tx = threadIdx.x;
    const int ty = threadIdx.y;
    const int tid = ty * BX + tx;

    const int tile_x = blockIdx.x * TW;
    const int tile_y = blockIdx.y * THRAW;
    const float* plane = x + (size_t)blockIdx.z * (H * W);

    // ---- Vectorized tile load ----
    // Interior: cols c in [4,132) -> gc = tile_x + (c-4), no wrap. 32 float4
    // groups per packed row; each group: 2x LDG.128 (rows r, r+16), pack to
    // 4x half2, 1x STS.128.
    {
        const float4* p4 = reinterpret_cast<const float4*>(plane);
        for (int t = tid; t < PROWS * (TW / 4); t += BX * BY) {
            int r = t >> 5;            // t / 32
            int g = t & 31;            // group: cols 4g..4g+3 of interior
            int gr0 = (tile_y + r) & (H - 1);
            int gr1 = (tile_y + r + PACK) & (H - 1);
            int col4 = (tile_x >> 2) + g;
            float4 a = p4[gr0 * (W / 4) + col4];
            float4 b = p4[gr1 * (W / 4) + col4];
            __half2 h0 = __floats2half2_rn(a.x, b.x);
            __half2 h1 = __floats2half2_rn(a.y, b.y);
            __half2 h2 = __floats2half2_rn(a.z, b.z);
            __half2 h3 = __floats2half2_rn(a.w, b.w);
            float4 st;
            st.x = *(float*)&h0; st.y = *(float*)&h1;
            st.z = *(float*)&h2; st.w = *(float*)&h3;
            *reinterpret_cast<float4*>(&s[r][4 + 4 * g]) = st;
        }
        // Halo: c in [0,4) and [132,136), scalar with wrap.
        for (int t = tid; t < PROWS * 8; t += BX * BY) {
            int r = t >> 3;
            int h = t & 7;
            int c = (h < 4) ? h : (128 + h);   // 0..3, 132..135
            int gr0 = (tile_y + r) & (H - 1);
            int gr1 = (tile_y + r + PACK) & (H - 1);
            int gc = (tile_x + c - 4) & (W - 1);
            s[r][c] = __floats2half2_rn(plane[gr0 * W + gc], plane[gr1 * W + gc]);
        }
    }
    __syncthreads();

    __half2 c2[RE];
    __half2 acc[RE];
#pragma unroll
    for (int e = 0; e < RE; e++) acc[e] = __floats2half2_rn(0.0f, 0.0f);

    __half2 win0[16], win1[16];

    LOADROW(win0, s[ty], tx);
    LOADROW(win1, s[ty + 1], tx);

#pragma unroll
    for (int e = 0; e < RE; e++) c2[e] = win0[4 + e];

    // k = 0: dl = 1..3 (symmetry covers negatives)
#pragma unroll
    for (int dl = 1; dl <= 3; dl++) {
#pragma unroll
        for (int e = 0; e < RE; e++) {
            __half2 d = __habs2(__hsub2(c2[e], win0[4 + e + dl]));
            acc[e] = __hadd2(acc[e], d);
        }
    }

    // Prefetch k=2 into win0; compute k=1 from win1.
    LOADROW(win0, s[ty + 2], tx);
#pragma unroll
    for (int dl = -3; dl <= 3; dl++) {
#pragma unroll
        for (int e = 0; e < RE; e++) {
            __half2 d = __habs2(__hsub2(c2[e], win1[4 + e + dl]));
            acc[e] = __hadd2(acc[e], d);
        }
    }

    // Prefetch k=3 into win1; compute k=2 from win0.
    LOADROW(win1, s[ty + 3], tx);
#pragma unroll
    for (int dl = -3; dl <= 3; dl++) {
#pragma unroll
        for (int e = 0; e < RE; e++) {
            __half2 d = __habs2(__hsub2(c2[e], win0[4 + e + dl]));
            acc[e] = __hadd2(acc[e], d);
        }
    }

    // k = 3 from win1.
#pragma unroll
    for (int dl = -3; dl <= 3; dl++) {
#pragma unroll
        for (int e = 0; e < RE; e++) {
            __half2 d = __habs2(__hsub2(c2[e], win1[4 + e + dl]));
            acc[e] = __hadd2(acc[e], d);
        }
    }

    // Widen to fp32 and reduce
    float accf = 0.0f;
#pragma unroll
    for (int e = 0; e < RE; e++) {
        float2 f = __half22float2(acc[e]);
        accf += f.x + f.y;
    }

#pragma unroll
    for (int o = 16; o > 0; o >>= 1) accf += __shfl_down_sync(0xFFFFFFFFu, accf, o);

    const int lane = tid & 31;
    const int wid = tid >> 5;
    if (lane == 0) warp_sums[wid] = accf;
    __syncthreads();

    if (tid == 0) {
        float bsum = 0.0f;
#pragma unroll
        for (int i = 0; i < (BX * BY) / 32; i++) bsum += warp_sums[i];
        int bidx = (blockIdx.z * gridDim.y + blockIdx.y) * gridDim.x + blockIdx.x;
        g_partials[bidx] = bsum;
        __threadfence();
        int done = atomicAdd(&g_ctr, 1);
        s_last = (done == NBLOCKS - 1) ? 1 : 0;
    }
    __syncthreads();

    // Last block reduces all partials (fixed order -> deterministic)
    if (s_last) {
        double t = 0.0;
        for (int i = tid; i < NBLOCKS; i += BX * BY) t += (double)g_partials[i];
#pragma unroll
        for (int o = 16; o > 0; o >>= 1) t += __shfl_down_sync(0xFFFFFFFFu, t, o);
        __shared__ double sm[(BX * BY) / 32];
        if (lane == 0) sm[wid] = t;
        __syncthreads();
        if (tid == 0) {
            double r = 0.0;
#pragma unroll
            for (int i = 0; i < (BX * BY) / 32; i++) r += sm[i];
            // symmetry factor 2; WEIGHT=0.1; N = 24*1024*1024
            out[0] = (float)(r * (0.2 / 25165824.0));
            atomicExch(&g_ctr, 0);  // reset for next graph replay
        }
    }
}

extern "C" void kernel_launch(void* const* d_in, const int* in_sizes, int n_in,
                              void* d_out, int out_size) {
    (void)in_sizes; (void)n_in; (void)out_size;
    const float* x = (const float*)d_in[0];
    float* out = (float*)d_out;

    dim3 grid(NBX, NBY, PLANES);
    dim3 block(BX, BY);
    btv_kernel<<<grid, block>>>(x, out);
}

// round 7
// speedup vs baseline: 2.7127x; 1.1850x over previous
#include <cuda_runtime.h>
#include <cuda_fp16.h>

#define H 1024
#define W 1024
#define PLANES 24              // 8 * 3
#define THRAW 32               // raw output rows per tile
#define PACK 16                // row-pack stride (.x = r, .y = r+16)
#define TW 128                 // tile cols
#define RE 8                   // cols per thread
#define BX 16
#define BY 16                  // packed rows per tile
#define PROWS (BY + 3)         // 19
#define SCOLS (TW + 8)         // 136
#define NBX (W / TW)           // 8
#define NBY (H / THRAW)        // 32
#define NT (NBX * NBY * PLANES)       // 6144 tiles
#define TPB 4                  // tiles per block (consecutive in x; 4 | NBX ok since px cycles 0..7)
#define NBLK (NT / TPB)        // 1536
#define NGRP (PROWS * (TW / 4))       // 608 interior float4-groups
#define NHALO (PROWS * 8)             // 152 halo half2 entries

__device__ float g_partials[NBLK];
__device__ int g_ctr = 0;

// Straight-order window load: compile-time register indices only.
#define LOADROW(wdst, srowp)                                                       \
    do {                                                                           \
        const float4* rowp = reinterpret_cast<const float4*>(srowp);               \
        float4 v0 = rowp[0], v1 = rowp[1], v2 = rowp[2], v3 = rowp[3];             \
        (wdst)[0] = *(__half2*)&v0.x;  (wdst)[1] = *(__half2*)&v0.y;               \
        (wdst)[2] = *(__half2*)&v0.z;  (wdst)[3] = *(__half2*)&v0.w;               \
        (wdst)[4] = *(__half2*)&v1.x;  (wdst)[5] = *(__half2*)&v1.y;               \
        (wdst)[6] = *(__half2*)&v1.z;  (wdst)[7] = *(__half2*)&v1.w;               \
        (wdst)[8] = *(__half2*)&v2.x;  (wdst)[9] = *(__half2*)&v2.y;               \
        (wdst)[10] = *(__half2*)&v2.z; (wdst)[11] = *(__half2*)&v2.w;              \
        (wdst)[12] = *(__half2*)&v3.x; (wdst)[13] = *(__half2*)&v3.y;              \
        (wdst)[14] = *(__half2*)&v3.z; (wdst)[15] = *(__half2*)&v3.w;              \
    } while (0)

// Prefetch one tile's data into registers (no smem writes).
#define PREFETCH(txile)                                                            \
    do {                                                                           \
        _Pragma("unroll")                                                          \
        for (int j = 0; j < 3; ++j) {                                              \
            int g = tid + j * 256;                                                 \
            if (g < NGRP) {                                                        \
                int r = g >> 5, gq = g & 31;                                       \
                int R0 = (tile_y + r) & (H - 1);                                   \
                int R1 = (tile_y + r + PACK) & (H - 1);                            \
                int col4 = ((txile) >> 2) + gq;                                    \
                pa[j] = p4[R0 * (W / 4) + col4];                                   \
                pb[j] = p4[R1 * (W / 4) + col4];                                   \
            }                                                                      \
        }                                                                          \
        if (tid < NHALO) {                                                         \
            int r = tid >> 3, hcp = tid & 7;                                       \
            int c = (hcp < 4) ? hcp : (128 + hcp);                                 \
            int R0 = (tile_y + r) & (H - 1);                                       \
            int R1 = (tile_y + r + PACK) & (H - 1);                                \
            int gc = ((txile) + c - 4) & (W - 1);                                  \
            pha = plane[R0 * W + gc];                                              \
            phb = plane[R1 * W + gc];                                              \
        }                                                                          \
    } while (0)

// Pack prefetched registers into smem buffer `buf`.
#define STORETILE(buf)                                                             \
    do {                                                                           \
        _Pragma("unroll")                                                          \
        for (int j = 0; j < 3; ++j) {                                              \
            int g = tid + j * 256;                                                 \
            if (g < NGRP) {                                                        \
                int r = g >> 5, gq = g & 31;                                       \
                __half2 h0 = __floats2half2_rn(pa[j].x, pb[j].x);                  \
                __half2 h1 = __floats2half2_rn(pa[j].y, pb[j].y);                  \
                __half2 h2 = __floats2half2_rn(pa[j].z, pb[j].z);                  \
                __half2 h3 = __floats2half2_rn(pa[j].w, pb[j].w);                  \
                float4 st;                                                         \
                st.x = *(float*)&h0; st.y = *(float*)&h1;                          \
                st.z = *(float*)&h2; st.w = *(float*)&h3;                          \
                *reinterpret_cast<float4*>(&s[buf][r][4 + 4 * gq]) = st;           \
            }                                                                      \
        }                                                                          \
        if (tid < NHALO) {                                                         \
            int r = tid >> 3, hcp = tid & 7;                                       \
            int c = (hcp < 4) ? hcp : (128 + hcp);                                 \
            s[buf][r][c] = __floats2half2_rn(pha, phb);                            \
        }                                                                          \
    } while (0)

__global__ __launch_bounds__(BX * BY, 3) void btv_kernel(const float* __restrict__ x,
                                                         float* __restrict__ out) {
    __shared__ __align__(16) __half2 s[2][PROWS][SCOLS];
    __shared__ float warp_sums[(BX * BY) / 32];
    __shared__ int s_last;

    const int tx = threadIdx.x;
    const int ty = threadIdx.y;
    const int tid = ty * BX + tx;

    const int t0 = blockIdx.x * TPB;
    // py, pz constant across the block's TPB tiles (TPB divides NBX's cycle)
    const int py = (t0 >> 3) & (NBY - 1);
    const int pz = t0 >> 8;
    const int tile_y = py * THRAW;
    const float* plane = x + (size_t)pz * (H * W);
    const float4* p4 = reinterpret_cast<const float4*>(plane);

    float4 pa[3], pb[3];
    float pha = 0.0f, phb = 0.0f;

    float accf = 0.0f;

    // Prologue: load tile 0 into buffer 0.
    {
        int tile_x0 = (t0 & (NBX - 1)) * TW;
        PREFETCH(tile_x0);
        STORETILE(0);
    }
    __syncthreads();

#pragma unroll
    for (int ti = 0; ti < TPB; ++ti) {
        const int cb = ti & 1;

        // Issue next tile's global loads before computing (latency overlap).
        if (ti + 1 < TPB) {
            int tile_xn = (((t0 + ti + 1) & (NBX - 1))) * TW;
            PREFETCH(tile_xn);
        }

        // ---- Compute current tile from s[cb] ----
        __half2 c2[RE];
        __half2 acc[RE];
#pragma unroll
        for (int e = 0; e < RE; e++) acc[e] = __floats2half2_rn(0.0f, 0.0f);

        __half2 win0[16], win1[16];
        LOADROW(win0, &s[cb][ty][tx * RE]);
        LOADROW(win1, &s[cb][ty + 1][tx * RE]);

#pragma unroll
        for (int e = 0; e < RE; e++) c2[e] = win0[4 + e];

        // k = 0: dl = 1..3 (symmetry covers negatives)
#pragma unroll
        for (int dl = 1; dl <= 3; dl++) {
#pragma unroll
            for (int e = 0; e < RE; e++) {
                __half2 d = __habs2(__hsub2(c2[e], win0[4 + e + dl]));
                acc[e] = __hadd2(acc[e], d);
            }
        }

        LOADROW(win0, &s[cb][ty + 2][tx * RE]);   // prefetch k=2
#pragma unroll
        for (int dl = -3; dl <= 3; dl++) {        // k=1 from win1
#pragma unroll
            for (int e = 0; e < RE; e++) {
                __half2 d = __habs2(__hsub2(c2[e], win1[4 + e + dl]));
                acc[e] = __hadd2(acc[e], d);
            }
        }

        LOADROW(win1, &s[cb][ty + 3][tx * RE]);   // prefetch k=3
#pragma unroll
        for (int dl = -3; dl <= 3; dl++) {        // k=2 from win0
#pragma unroll
            for (int e = 0; e < RE; e++) {
                __half2 d = __habs2(__hsub2(c2[e], win0[4 + e + dl]));
                acc[e] = __hadd2(acc[e], d);
            }
        }

#pragma unroll
        for (int dl = -3; dl <= 3; dl++) {        // k=3 from win1
#pragma unroll
            for (int e = 0; e < RE; e++) {
                __half2 d = __habs2(__hsub2(c2[e], win1[4 + e + dl]));
                acc[e] = __hadd2(acc[e], d);
            }
        }

        // Drain fp16 accumulators to fp32 (per tile: bounds error growth).
#pragma unroll
        for (int e = 0; e < RE; e++) {
            float2 f = __half22float2(acc[e]);
            accf += f.x + f.y;
        }

        // Write next tile into the other buffer, then barrier.
        if (ti + 1 < TPB) {
            STORETILE(cb ^ 1);
            __syncthreads();
        }
    }

    // ---- Block reduction ----
#pragma unroll
    for (int o = 16; o > 0; o >>= 1) accf += __shfl_down_sync(0xFFFFFFFFu, accf, o);

    const int lane = tid & 31;
    const int wid = tid >> 5;
    if (lane == 0) warp_sums[wid] = accf;
    __syncthreads();

    if (tid == 0) {
        float bsum = 0.0f;
#pragma unroll
        for (int i = 0; i < (BX * BY) / 32; i++) bsum += warp_sums[i];
        g_partials[blockIdx.x] = bsum;
        __threadfence();
        int done = atomicAdd(&g_ctr, 1);
        s_last = (done == NBLK - 1) ? 1 : 0;
    }
    __syncthreads();

    // Last block reduces all partials (fixed order -> deterministic)
    if (s_last) {
        double t = 0.0;
        for (int i = tid; i < NBLK; i += BX * BY) t += (double)g_partials[i];
#pragma unroll
        for (int o = 16; o > 0; o >>= 1) t += __shfl_down_sync(0xFFFFFFFFu, t, o);
        __shared__ double sm[(BX * BY) / 32];
        if (lane == 0) sm[wid] = t;
        __syncthreads();
        if (tid == 0) {
            double r = 0.0;
#pragma unroll
            for (int i = 0; i < (BX * BY) / 32; i++) r += sm[i];
            // symmetry factor 2; WEIGHT=0.1; N = 24*1024*1024
            out[0] = (float)(r * (0.2 / 25165824.0));
            atomicExch(&g_ctr, 0);  // reset for next graph replay
        }
    }
}

extern "C" void kernel_launch(void* const* d_in, const int* in_sizes, int n_in,
                              void* d_out, int out_size) {
    (void)in_sizes; (void)n_in; (void)out_size;
    const float* x = (const float*)d_in[0];
    float* out = (float*)d_out;

    btv_kernel<<<NBLK, dim3(BX, BY)>>>(x, out);
}

// round 8
// speedup vs baseline: 2.8218x; 1.0402x over previous
#include <cuda_runtime.h>
#include <cuda_fp16.h>

#define H 1024
#define W 1024
#define PLANES 24              // 8 * 3
#define THRAW 32               // raw output rows per tile
#define PACK 16                // row-pack stride (.x = r, .y = r+16)
#define TW 128                 // tile cols
#define RE 8                   // cols per thread
#define BX 16
#define BY 16                  // packed rows per tile
#define PROWS (BY + 3)         // 19
#define SCOLS (TW + 8)         // 136
#define NBX (W / TW)           // 8
#define NBY (H / THRAW)        // 32
#define NT (NBX * NBY * PLANES)       // 6144 tiles
#define TPB 4                  // tiles per block (consecutive in x)
#define NBLK (NT / TPB)        // 1536
#define NGRP (PROWS * (TW / 4))       // 608 interior float4-groups
#define NHALO (PROWS * 8)             // 152 halo half2 entries

__device__ float g_partials[NBLK];
__device__ int g_ctr = 0;

// Single window load: compile-time register indices only.
#define LOADROW(wdst, srowp)                                                       \
    do {                                                                           \
        const float4* rowp = reinterpret_cast<const float4*>(srowp);               \
        float4 v0 = rowp[0], v1 = rowp[1], v2 = rowp[2], v3 = rowp[3];             \
        (wdst)[0] = *(__half2*)&v0.x;  (wdst)[1] = *(__half2*)&v0.y;               \
        (wdst)[2] = *(__half2*)&v0.z;  (wdst)[3] = *(__half2*)&v0.w;               \
        (wdst)[4] = *(__half2*)&v1.x;  (wdst)[5] = *(__half2*)&v1.y;               \
        (wdst)[6] = *(__half2*)&v1.z;  (wdst)[7] = *(__half2*)&v1.w;               \
        (wdst)[8] = *(__half2*)&v2.x;  (wdst)[9] = *(__half2*)&v2.y;               \
        (wdst)[10] = *(__half2*)&v2.z; (wdst)[11] = *(__half2*)&v2.w;              \
        (wdst)[12] = *(__half2*)&v3.x; (wdst)[13] = *(__half2*)&v3.y;              \
        (wdst)[14] = *(__half2*)&v3.z; (wdst)[15] = *(__half2*)&v3.w;              \
    } while (0)

// Phase A: groups [0, 512) — unguarded (tid and tid+256 both < 512).
#define PREF_A(txile)                                                              \
    do {                                                                           \
        int g0 = tid, g1 = tid + 256;                                              \
        int r0 = g0 >> 5, q0 = g0 & 31, r1 = g1 >> 5, q1 = g1 & 31;                \
        aA0 = p4[(((tile_y + r0) & (H - 1)) * (W / 4)) + ((txile) >> 2) + q0];     \
        bA0 = p4[(((tile_y + r0 + PACK) & (H - 1)) * (W / 4)) + ((txile) >> 2) + q0]; \
        aA1 = p4[(((tile_y + r1) & (H - 1)) * (W / 4)) + ((txile) >> 2) + q1];     \
        bA1 = p4[(((tile_y + r1 + PACK) & (H - 1)) * (W / 4)) + ((txile) >> 2) + q1]; \
    } while (0)

#define STORE_A(buf)                                                               \
    do {                                                                           \
        int g0 = tid, g1 = tid + 256;                                              \
        int r0 = g0 >> 5, q0 = g0 & 31, r1 = g1 >> 5, q1 = g1 & 31;                \
        __half2 h0 = __floats2half2_rn(aA0.x, bA0.x);                              \
        __half2 h1 = __floats2half2_rn(aA0.y, bA0.y);                              \
        __half2 h2 = __floats2half2_rn(aA0.z, bA0.z);                              \
        __half2 h3 = __floats2half2_rn(aA0.w, bA0.w);                              \
        float4 st0;                                                                \
        st0.x = *(float*)&h0; st0.y = *(float*)&h1;                                \
        st0.z = *(float*)&h2; st0.w = *(float*)&h3;                                \
        *reinterpret_cast<float4*>(&s[buf][r0][4 + 4 * q0]) = st0;                 \
        h0 = __floats2half2_rn(aA1.x, bA1.x);                                      \
        h1 = __floats2half2_rn(aA1.y, bA1.y);                                      \
        h2 = __floats2half2_rn(aA1.z, bA1.z);                                      \
        h3 = __floats2half2_rn(aA1.w, bA1.w);                                      \
        float4 st1;                                                                \
        st1.x = *(float*)&h0; st1.y = *(float*)&h1;                                \
        st1.z = *(float*)&h2; st1.w = *(float*)&h3;                                \
        *reinterpret_cast<float4*>(&s[buf][r1][4 + 4 * q1]) = st1;                 \
    } while (0)

// Phase B: groups [512, 608) + halo.
#define PREF_B(txile)                                                              \
    do {                                                                           \
        if (tid < NGRP - 512) {                                                    \
            int g = tid + 512;                                                     \
            int r = g >> 5, q = g & 31;                                            \
            aB = p4[(((tile_y + r) & (H - 1)) * (W / 4)) + ((txile) >> 2) + q];    \
            bB = p4[(((tile_y + r + PACK) & (H - 1)) * (W / 4)) + ((txile) >> 2) + q]; \
        }                                                                          \
        if (tid < NHALO) {                                                         \
            int r = tid >> 3, hcp = tid & 7;                                       \
            int c = (hcp < 4) ? hcp : (128 + hcp);                                 \
            int gc = ((txile) + c - 4) & (W - 1);                                  \
            pha = plane[(((tile_y + r) & (H - 1)) * W) + gc];                      \
            phb = plane[(((tile_y + r + PACK) & (H - 1)) * W) + gc];               \
        }                                                                          \
    } while (0)

#define STORE_B(buf)                                                               \
    do {                                                                           \
        if (tid < NGRP - 512) {                                                    \
            int g = tid + 512;                                                     \
            int r = g >> 5, q = g & 31;                                            \
            __half2 h0 = __floats2half2_rn(aB.x, bB.x);                            \
            __half2 h1 = __floats2half2_rn(aB.y, bB.y);                            \
            __half2 h2 = __floats2half2_rn(aB.z, bB.z);                            \
            __half2 h3 = __floats2half2_rn(aB.w, bB.w);                            \
            float4 st;                                                             \
            st.x = *(float*)&h0; st.y = *(float*)&h1;                              \
            st.z = *(float*)&h2; st.w = *(float*)&h3;                              \
            *reinterpret_cast<float4*>(&s[buf][r][4 + 4 * q]) = st;                \
        }                                                                          \
        if (tid < NHALO) {                                                         \
            int r = tid >> 3, hcp = tid & 7;                                       \
            int c = (hcp < 4) ? hcp : (128 + hcp);                                 \
            s[buf][r][c] = __floats2half2_rn(pha, phb);                            \
        }                                                                          \
    } while (0)

__global__ __launch_bounds__(BX * BY, 4) void btv_kernel(const float* __restrict__ x,
                                                         float* __restrict__ out) {
    __shared__ __align__(16) __half2 s[2][PROWS][SCOLS];
    __shared__ float warp_sums[(BX * BY) / 32];
    __shared__ int s_last;

    const int tx = threadIdx.x;
    const int ty = threadIdx.y;
    const int tid = ty * BX + tx;

    const int t0 = blockIdx.x * TPB;
    const int py = (t0 >> 3) & (NBY - 1);
    const int pz = t0 >> 8;
    const int tile_y = py * THRAW;
    const float* plane = x + (size_t)pz * (H * W);
    const float4* p4 = reinterpret_cast<const float4*>(plane);

    float4 aA0, aA1, bA0, bA1, aB, bB;
    float pha = 0.0f, phb = 0.0f;
    float accf = 0.0f;

    // Prologue: tile 0 into buffer 0.
    {
        int tile_x0 = (t0 & (NBX - 1)) * TW;
        PREF_A(tile_x0);
        STORE_A(0);
        PREF_B(tile_x0);
        STORE_B(0);
    }
    __syncthreads();

#pragma unroll
    for (int ti = 0; ti < TPB; ++ti) {
        const int cb = ti & 1;
        const int has_next = (ti + 1 < TPB);
        const int tile_xn = (((t0 + ti + 1) & (NBX - 1))) * TW;

        if (has_next) PREF_A(tile_xn);

        __half2 c2[RE];
        __half2 acc[RE];
#pragma unroll
        for (int e = 0; e < RE; e++) acc[e] = __floats2half2_rn(0.0f, 0.0f);

        __half2 win[16];

        // k = 0: centers + dl = 1..3 (symmetry covers negatives)
        LOADROW(win, &s[cb][ty][tx * RE]);
#pragma unroll
        for (int e = 0; e < RE; e++) c2[e] = win[4 + e];
#pragma unroll
        for (int dl = 1; dl <= 3; dl++) {
#pragma unroll
            for (int e = 0; e < RE; e++) {
                __half2 d = __habs2(__hsub2(c2[e], win[4 + e + dl]));
                acc[e] = __hadd2(acc[e], d);
            }
        }

        // k = 1
        LOADROW(win, &s[cb][ty + 1][tx * RE]);
#pragma unroll
        for (int dl = -3; dl <= 3; dl++) {
#pragma unroll
            for (int e = 0; e < RE; e++) {
                __half2 d = __habs2(__hsub2(c2[e], win[4 + e + dl]));
                acc[e] = __hadd2(acc[e], d);
            }
        }

        if (has_next) {
            STORE_A(cb ^ 1);
            PREF_B(tile_xn);
        }

        // k = 2
        LOADROW(win, &s[cb][ty + 2][tx * RE]);
#pragma unroll
        for (int dl = -3; dl <= 3; dl++) {
#pragma unroll
            for (int e = 0; e < RE; e++) {
                __half2 d = __habs2(__hsub2(c2[e], win[4 + e + dl]));
                acc[e] = __hadd2(acc[e], d);
            }
        }

        // k = 3
        LOADROW(win, &s[cb][ty + 3][tx * RE]);
#pragma unroll
        for (int dl = -3; dl <= 3; dl++) {
#pragma unroll
            for (int e = 0; e < RE; e++) {
                __half2 d = __habs2(__hsub2(c2[e], win[4 + e + dl]));
                acc[e] = __hadd2(acc[e], d);
            }
        }

        // Drain fp16 accumulators to fp32 per tile.
#pragma unroll
        for (int e = 0; e < RE; e++) {
            float2 f = __half22float2(acc[e]);
            accf += f.x + f.y;
        }

        if (has_next) {
            STORE_B(cb ^ 1);
            __syncthreads();
        }
    }

    // ---- Block reduction ----
#pragma unroll
    for (int o = 16; o > 0; o >>= 1) accf += __shfl_down_sync(0xFFFFFFFFu, accf, o);

    const int lane = tid & 31;
    const int wid = tid >> 5;
    if (lane == 0) warp_sums[wid] = accf;
    __syncthreads();

    if (tid == 0) {
        float bsum = 0.0f;
#pragma unroll
        for (int i = 0; i < (BX * BY) / 32; i++) bsum += warp_sums[i];
        g_partials[blockIdx.x] = bsum;
        __threadfence();
        int done = atomicAdd(&g_ctr, 1);
        s_last = (done == NBLK - 1) ? 1 : 0;
    }
    __syncthreads();

    // Last block reduces all partials (fixed order -> deterministic)
    if (s_last) {
        double t = 0.0;
        for (int i = tid; i < NBLK; i += BX * BY) t += (double)g_partials[i];
#pragma unroll
        for (int o = 16; o > 0; o >>= 1) t += __shfl_down_sync(0xFFFFFFFFu, t, o);
        __shared__ double sm[(BX * BY) / 32];
        if (lane == 0) sm[wid] = t;
        __syncthreads();
        if (tid == 0) {
            double r = 0.0;
#pragma unroll
            for (int i = 0; i < (BX * BY) / 32; i++) r += sm[i];
            // symmetry factor 2; WEIGHT=0.1; N = 24*1024*1024
            out[0] = (float)(r * (0.2 / 25165824.0));
            atomicExch(&g_ctr, 0);  // reset for next graph replay
        }
    }
}

extern "C" void kernel_launch(void* const* d_in, const int* in_sizes, int n_in,
                              void* d_out, int out_size) {
    (void)in_sizes; (void)n_in; (void)out_size;
    const float* x = (const float*)d_in[0];
    float* out = (float*)d_out;

    btv_kernel<<<NBLK, dim3(BX, BY)>>>(x, out);
}

// round 9
// speedup vs baseline: 2.8824x; 1.0215x over previous
#include <cuda_runtime.h>
#include <cuda_fp16.h>

#define H 1024
#define W 1024
#define PLANES 24              // 8 * 3
#define THRAW 32               // raw output rows per tile
#define PACK 16                // row-pack stride (.x = r, .y = r+16)
#define TW 128                 // tile cols
#define RE 8                   // cols per thread
#define BX 16
#define BY 16                  // packed rows per tile
#define PROWS (BY + 3)         // 19
#define SCOLS (TW + 8)         // 136
#define NBX (W / TW)           // 8
#define NBY (H / THRAW)        // 32
#define NT (NBX * NBY * PLANES)       // 6144 tiles
#define GRIDB 592              // 148 SMs x 4 resident blocks: persistent grid
#define NGRP (PROWS * (TW / 4))       // 608 interior float4-groups
#define NHALO (PROWS * 8)             // 152 halo half2 entries

__device__ float g_partials[GRIDB];
__device__ int g_ctr = 0;

// Single window load: compile-time register indices only.
#define LOADROW(wdst, srowp)                                                       \
    do {                                                                           \
        const float4* rowp = reinterpret_cast<const float4*>(srowp);               \
        float4 v0 = rowp[0], v1 = rowp[1], v2 = rowp[2], v3 = rowp[3];             \
        (wdst)[0] = *(__half2*)&v0.x;  (wdst)[1] = *(__half2*)&v0.y;               \
        (wdst)[2] = *(__half2*)&v0.z;  (wdst)[3] = *(__half2*)&v0.w;               \
        (wdst)[4] = *(__half2*)&v1.x;  (wdst)[5] = *(__half2*)&v1.y;               \
        (wdst)[6] = *(__half2*)&v1.z;  (wdst)[7] = *(__half2*)&v1.w;               \
        (wdst)[8] = *(__half2*)&v2.x;  (wdst)[9] = *(__half2*)&v2.y;               \
        (wdst)[10] = *(__half2*)&v2.z; (wdst)[11] = *(__half2*)&v2.w;              \
        (wdst)[12] = *(__half2*)&v3.x; (wdst)[13] = *(__half2*)&v3.y;              \
        (wdst)[14] = *(__half2*)&v3.z; (wdst)[15] = *(__half2*)&v3.w;              \
    } while (0)

// Phase A: groups [0, 512) — unguarded. Coords recomputed from tile index
// (not kept live across compute) to hold register pressure down.
#define PREF_A(tt)                                                                 \
    do {                                                                           \
        int px_ = (tt) & (NBX - 1), py_ = ((tt) >> 3) & (NBY - 1), pz_ = (tt) >> 8; \
        int txx = px_ * TW, tyy = py_ * THRAW;                                     \
        const float4* pp = reinterpret_cast<const float4*>(x + (size_t)pz_ * (H * W)); \
        int g0 = tid, g1 = tid + 256;                                              \
        int r0 = g0 >> 5, q0 = g0 & 31, r1 = g1 >> 5, q1 = g1 & 31;                \
        aA0 = pp[(((tyy + r0) & (H - 1)) * (W / 4)) + (txx >> 2) + q0];            \
        bA0 = pp[(((tyy + r0 + PACK) & (H - 1)) * (W / 4)) + (txx >> 2) + q0];     \
        aA1 = pp[(((tyy + r1) & (H - 1)) * (W / 4)) + (txx >> 2) + q1];            \
        bA1 = pp[(((tyy + r1 + PACK) & (H - 1)) * (W / 4)) + (txx >> 2) + q1];     \
    } while (0)

#define STORE_A(buf)                                                               \
    do {                                                                           \
        int g0 = tid, g1 = tid + 256;                                              \
        int r0 = g0 >> 5, q0 = g0 & 31, r1 = g1 >> 5, q1 = g1 & 31;                \
        __half2 h0 = __floats2half2_rn(aA0.x, bA0.x);                              \
        __half2 h1 = __floats2half2_rn(aA0.y, bA0.y);                              \
        __half2 h2 = __floats2half2_rn(aA0.z, bA0.z);                              \
        __half2 h3 = __floats2half2_rn(aA0.w, bA0.w);                              \
        float4 st0;                                                                \
        st0.x = *(float*)&h0; st0.y = *(float*)&h1;                                \
        st0.z = *(float*)&h2; st0.w = *(float*)&h3;                                \
        *reinterpret_cast<float4*>(&s[buf][r0][4 + 4 * q0]) = st0;                 \
        h0 = __floats2half2_rn(aA1.x, bA1.x);                                      \
        h1 = __floats2half2_rn(aA1.y, bA1.y);                                      \
        h2 = __floats2half2_rn(aA1.z, bA1.z);                                      \
        h3 = __floats2half2_rn(aA1.w, bA1.w);                                      \
        float4 st1;                                                                \
        st1.x = *(float*)&h0; st1.y = *(float*)&h1;                                \
        st1.z = *(float*)&h2; st1.w = *(float*)&h3;                                \
        *reinterpret_cast<float4*>(&s[buf][r1][4 + 4 * q1]) = st1;                 \
    } while (0)

// Phase B: groups [512, 608) + halo.
#define PREF_B(tt)                                                                 \
    do {                                                                           \
        int px_ = (tt) & (NBX - 1), py_ = ((tt) >> 3) & (NBY - 1), pz_ = (tt) >> 8; \
        int txx = px_ * TW, tyy = py_ * THRAW;                                     \
        const float* pl = x + (size_t)pz_ * (H * W);                               \
        const float4* pp = reinterpret_cast<const float4*>(pl);                    \
        if (tid < NGRP - 512) {                                                    \
            int g = tid + 512;                                                     \
            int r = g >> 5, q = g & 31;                                            \
            aB = pp[(((tyy + r) & (H - 1)) * (W / 4)) + (txx >> 2) + q];           \
            bB = pp[(((tyy + r + PACK) & (H - 1)) * (W / 4)) + (txx >> 2) + q];    \
        }                                                                          \
        if (tid < NHALO) {                                                         \
            int r = tid >> 3, hcp = tid & 7;                                       \
            int c = (hcp < 4) ? hcp : (128 + hcp);                                 \
            int gc = (txx + c - 4) & (W - 1);                                      \
            pha = pl[(((tyy + r) & (H - 1)) * W) + gc];                            \
            phb = pl[(((tyy + r + PACK) & (H - 1)) * W) + gc];                     \
        }                                                                          \
    } while (0)

#define STORE_B(buf)                                                               \
    do {                                                                           \
        if (tid < NGRP - 512) {                                                    \
            int g = tid + 512;                                                     \
            int r = g >> 5, q = g & 31;                                            \
            __half2 h0 = __floats2half2_rn(aB.x, bB.x);                            \
            __half2 h1 = __floats2half2_rn(aB.y, bB.y);                            \
            __half2 h2 = __floats2half2_rn(aB.z, bB.z);                            \
            __half2 h3 = __floats2half2_rn(aB.w, bB.w);                            \
            float4 st;                                                             \
            st.x = *(float*)&h0; st.y = *(float*)&h1;                              \
            st.z = *(float*)&h2; st.w = *(float*)&h3;                              \
            *reinterpret_cast<float4*>(&s[buf][r][4 + 4 * q]) = st;                \
        }                                                                          \
        if (tid < NHALO) {                                                         \
            int r = tid >> 3, hcp = tid & 7;                                       \
            int c = (hcp < 4) ? hcp : (128 + hcp);                                 \
            s[buf][r][c] = __floats2half2_rn(pha, phb);                            \
        }                                                                          \
    } while (0)

__global__ __launch_bounds__(BX * BY, 4) void btv_kernel(const float* __restrict__ x,
                                                         float* __restrict__ out) {
    __shared__ __align__(16) __half2 s[2][PROWS][SCOLS];
    __shared__ float warp_sums[(BX * BY) / 32];
    __shared__ int s_last;

    const int tx = threadIdx.x;
    const int ty = threadIdx.y;
    const int tid = ty * BX + tx;

    float4 aA0, aA1, bA0, bA1, aB, bB;
    float pha = 0.0f, phb = 0.0f;
    float accf = 0.0f;

    int t = blockIdx.x;

    // Prologue: first tile into buffer 0.
    PREF_A(t);
    STORE_A(0);
    PREF_B(t);
    STORE_B(0);
    __syncthreads();

    int cb = 0;
#pragma unroll 1
    for (; t < NT; t += GRIDB) {
        const int tn = t + GRIDB;
        const bool hn = (tn < NT);

        if (hn) PREF_A(tn);

        __half2 c2[RE];
        __half2 acc[RE];
#pragma unroll
        for (int e = 0; e < RE; e++) acc[e] = __floats2half2_rn(0.0f, 0.0f);

        __half2 win[16];

        // k = 0: centers + dl = 1..3 (symmetry covers negatives)
        LOADROW(win, &s[cb][ty][tx * RE]);
#pragma unroll
        for (int e = 0; e < RE; e++) c2[e] = win[4 + e];
#pragma unroll
        for (int dl = 1; dl <= 3; dl++) {
#pragma unroll
            for (int e = 0; e < RE; e++) {
                __half2 d = __habs2(__hsub2(c2[e], win[4 + e + dl]));
                acc[e] = __hadd2(acc[e], d);
            }
        }

        // k = 1
        LOADROW(win, &s[cb][ty + 1][tx * RE]);
#pragma unroll
        for (int dl = -3; dl <= 3; dl++) {
#pragma unroll
            for (int e = 0; e < RE; e++) {
                __half2 d = __habs2(__hsub2(c2[e], win[4 + e + dl]));
                acc[e] = __hadd2(acc[e], d);
            }
        }

        if (hn) {
            STORE_A(cb ^ 1);
            PREF_B(tn);
        }

        // k = 2
        LOADROW(win, &s[cb][ty + 2][tx * RE]);
#pragma unroll
        for (int dl = -3; dl <= 3; dl++) {
#pragma unroll
            for (int e = 0; e < RE; e++) {
                __half2 d = __habs2(__hsub2(c2[e], win[4 + e + dl]));
                acc[e] = __hadd2(acc[e], d);
            }
        }

        // k = 3
        LOADROW(win, &s[cb][ty + 3][tx * RE]);
#pragma unroll
        for (int dl = -3; dl <= 3; dl++) {
#pragma unroll
            for (int e = 0; e < RE; e++) {
                __half2 d = __habs2(__hsub2(c2[e], win[4 + e + dl]));
                acc[e] = __hadd2(acc[e], d);
            }
        }

        // Drain fp16 accumulators to fp32 per tile.
#pragma unroll
        for (int e = 0; e < RE; e++) {
            float2 f = __half22float2(acc[e]);
            accf += f.x + f.y;
        }

        if (hn) {
            STORE_B(cb ^ 1);
            __syncthreads();
        }
        cb ^= 1;
    }

    // ---- Block reduction ----
#pragma unroll
    for (int o = 16; o > 0; o >>= 1) accf += __shfl_down_sync(0xFFFFFFFFu, accf, o);

    const int lane = tid & 31;
    const int wid = tid >> 5;
    if (lane == 0) warp_sums[wid] = accf;
    __syncthreads();

    if (tid == 0) {
        float bsum = 0.0f;
#pragma unroll
        for (int i = 0; i < (BX * BY) / 32; i++) bsum += warp_sums[i];
        g_partials[blockIdx.x] = bsum;
        __threadfence();
        int done = atomicAdd(&g_ctr, 1);
        s_last = (done == GRIDB - 1) ? 1 : 0;
    }
    __syncthreads();

    // Last block reduces all partials (fixed order -> deterministic)
    if (s_last) {
        double td = 0.0;
        for (int i = tid; i < GRIDB; i += BX * BY) td += (double)g_partials[i];
#pragma unroll
        for (int o = 16; o > 0; o >>= 1) td += __shfl_down_sync(0xFFFFFFFFu, td, o);
        __shared__ double sm[(BX * BY) / 32];
        if (lane == 0) sm[wid] = td;
        __syncthreads();
        if (tid == 0) {
            double r = 0.0;
#pragma unroll
            for (int i = 0; i < (BX * BY) / 32; i++) r += sm[i];
            // symmetry factor 2; WEIGHT=0.1; N = 24*1024*1024
            out[0] = (float)(r * (0.2 / 25165824.0));
            atomicExch(&g_ctr, 0);  // reset for next graph replay
        }
    }
}

extern "C" void kernel_launch(void* const* d_in, const int* in_sizes, int n_in,
                              void* d_out, int out_size) {
    (void)in_sizes; (void)n_in; (void)out_size;
    const float* x = (const float*)d_in[0];
    float* out = (float*)d_out;

    btv_kernel<<<GRIDB, dim3(BX, BY)>>>(x, out);
}

// round 10
// speedup vs baseline: 2.9381x; 1.0193x over previous
#include <cuda_runtime.h>
#include <cuda_fp16.h>

#define H 1024
#define W 1024
#define PLANES 24              // 8 * 3
#define THRAW 32               // raw output rows per tile
#define PACK 16                // row-pack stride (.x = r, .y = r+16)
#define TW 128                 // tile cols
#define RE 8                   // cols per thread
#define BX 16
#define BY 16                  // packed rows per tile
#define PROWS (BY + 3)         // 19
#define SCOLS (TW + 8)         // 136 half2 = 34 16B-chunks per row
#define NBX (W / TW)           // 8
#define NBY (H / THRAW)        // 32
#define NT (NBX * NBY * PLANES)       // 6144 tiles
#define GRIDB 592              // 148 SMs x 4 resident blocks: persistent grid
#define NGRP (PROWS * (TW / 4))       // 608 interior float4-groups
#define NHALO (PROWS * 8)             // 152 halo half2 entries

// Even/odd chunk de-interleave: physical slot i (0..31 interior) holds logical
// gmem float4 group QPERM(i). LDS window chunks become physically contiguous.
#define QPERM(i) (((i) < 16) ? (2 * (i) + 1) : (2 * ((i) - 16)))

__device__ float g_partials[GRIDB];
__device__ int g_ctr = 0;

// Window load from de-interleaved layout. Physical chunks: tx, 17+tx, tx+1, 18+tx
// hold logical chunks 2tx, 2tx+1, 2tx+2, 2tx+3 (cols 8tx..8tx+15).
#define LOADROW(wdst, srow, txv)                                                   \
    do {                                                                           \
        const float4* rowp = reinterpret_cast<const float4*>(&(srow)[0]);          \
        float4 v0 = rowp[(txv)];                                                   \
        float4 v1 = rowp[17 + (txv)];                                              \
        float4 v2 = rowp[(txv) + 1];                                               \
        float4 v3 = rowp[18 + (txv)];                                              \
        (wdst)[0] = *(__half2*)&v0.x;  (wdst)[1] = *(__half2*)&v0.y;               \
        (wdst)[2] = *(__half2*)&v0.z;  (wdst)[3] = *(__half2*)&v0.w;               \
        (wdst)[4] = *(__half2*)&v1.x;  (wdst)[5] = *(__half2*)&v1.y;               \
        (wdst)[6] = *(__half2*)&v1.z;  (wdst)[7] = *(__half2*)&v1.w;               \
        (wdst)[8] = *(__half2*)&v2.x;  (wdst)[9] = *(__half2*)&v2.y;               \
        (wdst)[10] = *(__half2*)&v2.z; (wdst)[11] = *(__half2*)&v2.w;              \
        (wdst)[12] = *(__half2*)&v3.x; (wdst)[13] = *(__half2*)&v3.y;              \
        (wdst)[14] = *(__half2*)&v3.z; (wdst)[15] = *(__half2*)&v3.w;              \
    } while (0)

// Phase A: physical slots [0, 512) — unguarded.
#define PREF_A(tt)                                                                 \
    do {                                                                           \
        int px_ = (tt) & (NBX - 1), py_ = ((tt) >> 3) & (NBY - 1), pz_ = (tt) >> 8; \
        int txx = px_ * TW, tyy = py_ * THRAW;                                     \
        const float4* pp = reinterpret_cast<const float4*>(x + (size_t)pz_ * (H * W)); \
        int g0 = tid, g1 = tid + 256;                                              \
        int r0 = g0 >> 5, i0 = g0 & 31, r1 = g1 >> 5, i1 = g1 & 31;                \
        int q0 = QPERM(i0), q1 = QPERM(i1);                                        \
        aA0 = pp[(((tyy + r0) & (H - 1)) * (W / 4)) + (txx >> 2) + q0];            \
        bA0 = pp[(((tyy + r0 + PACK) & (H - 1)) * (W / 4)) + (txx >> 2) + q0];     \
        aA1 = pp[(((tyy + r1) & (H - 1)) * (W / 4)) + (txx >> 2) + q1];            \
        bA1 = pp[(((tyy + r1 + PACK) & (H - 1)) * (W / 4)) + (txx >> 2) + q1];     \
    } while (0)

// Store to physical slot: byte 16*(1+i) == half2 col 4+4i (same form as before).
#define STORE_A(buf)                                                               \
    do {                                                                           \
        int g0 = tid, g1 = tid + 256;                                              \
        int r0 = g0 >> 5, i0 = g0 & 31, r1 = g1 >> 5, i1 = g1 & 31;                \
        __half2 h0 = __floats2half2_rn(aA0.x, bA0.x);                              \
        __half2 h1 = __floats2half2_rn(aA0.y, bA0.y);                              \
        __half2 h2 = __floats2half2_rn(aA0.z, bA0.z);                              \
        __half2 h3 = __floats2half2_rn(aA0.w, bA0.w);                              \
        float4 st0;                                                                \
        st0.x = *(float*)&h0; st0.y = *(float*)&h1;                                \
        st0.z = *(float*)&h2; st0.w = *(float*)&h3;                                \
        *reinterpret_cast<float4*>(&s[buf][r0][4 + 4 * i0]) = st0;                 \
        h0 = __floats2half2_rn(aA1.x, bA1.x);                                      \
        h1 = __floats2half2_rn(aA1.y, bA1.y);                                      \
        h2 = __floats2half2_rn(aA1.z, bA1.z);                                      \
        h3 = __floats2half2_rn(aA1.w, bA1.w);                                      \
        float4 st1;                                                                \
        st1.x = *(float*)&h0; st1.y = *(float*)&h1;                                \
        st1.z = *(float*)&h2; st1.w = *(float*)&h3;                                \
        *reinterpret_cast<float4*>(&s[buf][r1][4 + 4 * i1]) = st1;                 \
    } while (0)

// Phase B: physical slots [512, 608) + halo (halo chunks 0 and 33 map to
// themselves under the permutation -> unchanged addressing).
#define PREF_B(tt)                                                                 \
    do {                                                                           \
        int px_ = (tt) & (NBX - 1), py_ = ((tt) >> 3) & (NBY - 1), pz_ = (tt) >> 8; \
        int txx = px_ * TW, tyy = py_ * THRAW;                                     \
        const float* pl = x + (size_t)pz_ * (H * W);                               \
        const float4* pp = reinterpret_cast<const float4*>(pl);                    \
        if (tid < NGRP - 512) {                                                    \
            int g = tid + 512;                                                     \
            int r = g >> 5, i = g & 31;                                            \
            int q = QPERM(i);                                                      \
            aB = pp[(((tyy + r) & (H - 1)) * (W / 4)) + (txx >> 2) + q];           \
            bB = pp[(((tyy + r + PACK) & (H - 1)) * (W / 4)) + (txx >> 2) + q];    \
        }                                                                          \
        if (tid < NHALO) {                                                         \
            int r = tid >> 3, hcp = tid & 7;                                       \
            int c = (hcp < 4) ? hcp : (128 + hcp);                                 \
            int gc = (txx + c - 4) & (W - 1);                                      \
            pha = pl[(((tyy + r) & (H - 1)) * W) + gc];                            \
            phb = pl[(((tyy + r + PACK) & (H - 1)) * W) + gc];                     \
        }                                                                          \
    } while (0)

#define STORE_B(buf)                                                               \
    do {                                                                           \
        if (tid < NGRP - 512) {                                                    \
            int g = tid + 512;                                                     \
            int r = g >> 5, i = g & 31;                                            \
            __half2 h0 = __floats2half2_rn(aB.x, bB.x);                            \
            __half2 h1 = __floats2half2_rn(aB.y, bB.y);                            \
            __half2 h2 = __floats2half2_rn(aB.z, bB.z);                            \
            __half2 h3 = __floats2half2_rn(aB.w, bB.w);                            \
            float4 st;                                                             \
            st.x = *(float*)&h0; st.y = *(float*)&h1;                              \
            st.z = *(float*)&h2; st.w = *(float*)&h3;                              \
            *reinterpret_cast<float4*>(&s[buf][r][4 + 4 * i]) = st;                \
        }                                                                          \
        if (tid < NHALO) {                                                         \
            int r = tid >> 3, hcp = tid & 7;                                       \
            int c = (hcp < 4) ? hcp : (128 + hcp);                                 \
            s[buf][r][c] = __floats2half2_rn(pha, phb);                            \
        }                                                                          \
    } while (0)

__global__ __launch_bounds__(BX * BY, 4) void btv_kernel(const float* __restrict__ x,
                                                         float* __restrict__ out) {
    __shared__ __align__(16) __half2 s[2][PROWS][SCOLS];
    __shared__ float warp_sums[(BX * BY) / 32];
    __shared__ int s_last;

    const int tx = threadIdx.x;
    const int ty = threadIdx.y;
    const int tid = ty * BX + tx;

    float4 aA0, aA1, bA0, bA1, aB, bB;
    float pha = 0.0f, phb = 0.0f;
    float accf = 0.0f;

    int t = blockIdx.x;

    // Prologue: first tile into buffer 0.
    PREF_A(t);
    STORE_A(0);
    PREF_B(t);
    STORE_B(0);
    __syncthreads();

    int cb = 0;
#pragma unroll 1
    for (; t < NT; t += GRIDB) {
        const int tn = t + GRIDB;
        const bool hn = (tn < NT);

        if (hn) PREF_A(tn);

        __half2 c2[RE];
        __half2 acc[RE];
#pragma unroll
        for (int e = 0; e < RE; e++) acc[e] = __floats2half2_rn(0.0f, 0.0f);

        __half2 win[16];

        // k = 0: centers + dl = 1..3 (symmetry covers negatives)
        LOADROW(win, s[cb][ty], tx);
#pragma unroll
        for (int e = 0; e < RE; e++) c2[e] = win[4 + e];
#pragma unroll
        for (int dl = 1; dl <= 3; dl++) {
#pragma unroll
            for (int e = 0; e < RE; e++) {
                __half2 d = __habs2(__hsub2(c2[e], win[4 + e + dl]));
                acc[e] = __hadd2(acc[e], d);
            }
        }

        // k = 1
        LOADROW(win, s[cb][ty + 1], tx);
#pragma unroll
        for (int dl = -3; dl <= 3; dl++) {
#pragma unroll
            for (int e = 0; e < RE; e++) {
                __half2 d = __habs2(__hsub2(c2[e], win[4 + e + dl]));
                acc[e] = __hadd2(acc[e], d);
            }
        }

        if (hn) {
            STORE_A(cb ^ 1);
            PREF_B(tn);
        }

        // k = 2
        LOADROW(win, s[cb][ty + 2], tx);
#pragma unroll
        for (int dl = -3; dl <= 3; dl++) {
#pragma unroll
            for (int e = 0; e < RE; e++) {
                __half2 d = __habs2(__hsub2(c2[e], win[4 + e + dl]));
                acc[e] = __hadd2(acc[e], d);
            }
        }

        // k = 3
        LOADROW(win, s[cb][ty + 3], tx);
#pragma unroll
        for (int dl = -3; dl <= 3; dl++) {
#pragma unroll
            for (int e = 0; e < RE; e++) {
                __half2 d = __habs2(__hsub2(c2[e], win[4 + e + dl]));
                acc[e] = __hadd2(acc[e], d);
            }
        }

        // Drain fp16 accumulators to fp32 per tile.
#pragma unroll
        for (int e = 0; e < RE; e++) {
            float2 f = __half22float2(acc[e]);
            accf += f.x + f.y;
        }

        if (hn) {
            STORE_B(cb ^ 1);
            __syncthreads();
        }
        cb ^= 1;
    }

    // ---- Block reduction ----
#pragma unroll
    for (int o = 16; o > 0; o >>= 1) accf += __shfl_down_sync(0xFFFFFFFFu, accf, o);

    const int lane = tid & 31;
    const int wid = tid >> 5;
    if (lane == 0) warp_sums[wid] = accf;
    __syncthreads();

    if (tid == 0) {
        float bsum = 0.0f;
#pragma unroll
        for (int i = 0; i < (BX * BY) / 32; i++) bsum += warp_sums[i];
        g_partials[blockIdx.x] = bsum;
        __threadfence();
        int done = atomicAdd(&g_ctr, 1);
        s_last = (done == GRIDB - 1) ? 1 : 0;
    }
    __syncthreads();

    // Last block reduces all partials (fixed order -> deterministic)
    if (s_last) {
        double td = 0.0;
        for (int i = tid; i < GRIDB; i += BX * BY) td += (double)g_partials[i];
#pragma unroll
        for (int o = 16; o > 0; o >>= 1) td += __shfl_down_sync(0xFFFFFFFFu, td, o);
        __shared__ double sm[(BX * BY) / 32];
        if (lane == 0) sm[wid] = td;
        __syncthreads();
        if (tid == 0) {
            double r = 0.0;
#pragma unroll
            for (int i = 0; i < (BX * BY) / 32; i++) r += sm[i];
            // symmetry factor 2; WEIGHT=0.1; N = 24*1024*1024
            out[0] = (float)(r * (0.2 / 25165824.0));
            atomicExch(&g_ctr, 0);  // reset for next graph replay
        }
    }
}

extern "C" void kernel_launch(void* const* d_in, const int* in_sizes, int n_in,
                              void* d_out, int out_size) {
    (void)in_sizes; (void)n_in; (void)out_size;
    const float* x = (const float*)d_in[0];
    float* out = (float*)d_out;

    btv_kernel<<<GRIDB, dim3(BX, BY)>>>(x, out);
}